// round 4
// baseline (speedup 1.0000x reference)
#include <cuda_runtime.h>
#include <math.h>

// MultiScaleLMN clockwork RNN — fp32 incremental scan in ONE persistent kernel.
// T=256, B=64, IN=512, HID=1024, MEM=256, NMOD=8, M=2048
#define T_    256
#define B_    64
#define IN_   512
#define HID_  1024
#define MEM_  256
#define NMOD_ 8
#define M_    2048
#define NBMAX 148     // persistent grid cap: one CTA per SM
#define NT    256

// ---------------- persistent device scratch (static allocation only) ----------------
__device__ __align__(16) float g_P[(size_t)T_ * B_ * HID_];      // x@Wxh precompute
__device__ __align__(16) float g_h[B_ * HID_];                   // h_t
__device__ __align__(16) float g_G[B_ * HID_];                   // folded m@Wmh^T
__device__ __align__(16) float g_Gpart[8 * B_ * HID_];           // pending dm@Wmh^T split-K partials
__device__ __align__(16) float g_U[B_ * M_];                     // folded m@Wmm^T
__device__ __align__(16) float g_Upart[NMOD_ * 8 * B_ * MEM_];   // pending dm@Wmm^T partials [bj][s][b][jc]
__device__ __align__(16) float g_m[B_ * M_];                     // memory state
__device__ __align__(16) float g_dm[B_ * M_];                    // delta m (active cols of last step)
__device__ __align__(16) float g_Hpart[16 * B_ * M_];            // h@Whm^T split-K partials [s][b][j]
__device__ unsigned g_arrive[NBMAX * 32];                        // barrier arrival slots (128B apart)
__device__ unsigned g_go;                                        // barrier release generation

// ---------------------------------------------------------------------------
// Software grid barrier (all gridDim.x CTAs resident, 1/SM).
// Producer: __syncthreads -> thread0 fence(gpu) -> flag store.
// CTA0 warp0 polls all flags, fences (acquire side), releases via g_go.
// Consumers: thread0 spins on g_go, fence, __syncthreads.
// ---------------------------------------------------------------------------
__device__ __forceinline__ void gsync(unsigned ep) {
    __syncthreads();
    if (threadIdx.x == 0) {
        __threadfence();
        *((volatile unsigned*)&g_arrive[blockIdx.x * 32]) = ep;
    }
    if (blockIdx.x == 0) {
        if (threadIdx.x < 32) {
            const int n = gridDim.x;
            for (;;) {
                bool mine = true;
                for (int s = threadIdx.x; s < n; s += 32)
                    if (*((volatile unsigned*)&g_arrive[s * 32]) < ep) mine = false;
                if (__all_sync(0xffffffffu, mine)) break;
            }
            __threadfence();   // acquire side: order flag-observe before data reads
            if (threadIdx.x == 0) {
                *((volatile unsigned*)&g_go) = ep;
            }
        }
    } else {
        if (threadIdx.x == 0) {
            while (*((volatile unsigned*)&g_go) < ep) {}
            __threadfence();
        }
    }
    __syncthreads();
}

// ---------------------------------------------------------------------------
// Tile GEMM: out[64 x 32] = A[64 x K] * W[32 x K]^T  (overwrite), 256 threads,
// BK=32, microtile 4 rows x 2 cols.
// Staging layouts ([kk][elem], XOR-swizzled vector groups):
//   As phys = kk*64 + (((r>>2) ^ kk) & 15)*4 + (r&3)   -> float4 loads, 4-way STS
//   Ws phys = kk*32 + (((c>>1) ^ kk) & 15)*2 + (c&1)   -> float2 loads, 2-way STS
// Loads are broadcast/conflict-free. smem: 3072 floats.
// ---------------------------------------------------------------------------
__device__ __forceinline__ void tile64x32(
    const float* __restrict__ A, int lda,
    const float* __restrict__ W, int ldw, int K,
    float* __restrict__ out, int ldo, float* __restrict__ sm)
{
    float* As = sm;           // 2048 floats
    float* Ws = sm + 2048;    // 1024 floats
    const int tid = threadIdx.x;
    const int rg = tid >> 4;      // 0..15 -> r0 = rg*4
    const int cg = tid & 15;      // 0..15 -> c0 = cg*2

    float a00 = 0.f, a01 = 0.f, a10 = 0.f, a11 = 0.f;
    float a20 = 0.f, a21 = 0.f, a30 = 0.f, a31 = 0.f;

    for (int kt = 0; kt < K; kt += 32) {
        #pragma unroll
        for (int i = 0; i < 8; i++) {            // A: 64 rows x 32 kk
            int idx = tid + (i << 8);
            int r = idx >> 5, kk = idx & 31;     // coalesced over kk
            As[(kk << 6) + ((((r >> 2) ^ kk) & 15) << 2) + (r & 3)] =
                A[(size_t)r * lda + kt + kk];
        }
        #pragma unroll
        for (int i = 0; i < 4; i++) {            // W: 32 cols x 32 kk
            int idx = tid + (i << 8);
            int c = idx >> 5, kk = idx & 31;
            Ws[(kk << 5) + ((((c >> 1) ^ kk) & 15) << 1) + (c & 1)] =
                W[(size_t)c * ldw + kt + kk];
        }
        __syncthreads();
        #pragma unroll
        for (int kk = 0; kk < 32; kk++) {
            float4 a = *reinterpret_cast<const float4*>(
                &As[(kk << 6) + (((rg ^ kk) & 15) << 2)]);
            float2 w = *reinterpret_cast<const float2*>(
                &Ws[(kk << 5) + (((cg ^ kk) & 15) << 1)]);
            a00 += a.x * w.x; a01 += a.x * w.y;
            a10 += a.y * w.x; a11 += a.y * w.y;
            a20 += a.z * w.x; a21 += a.z * w.y;
            a30 += a.w * w.x; a31 += a.w * w.y;
        }
        __syncthreads();
    }
    const int r0 = rg << 2, c0 = cg << 1;
    *reinterpret_cast<float2*>(&out[(size_t)(r0 + 0) * ldo + c0]) = make_float2(a00, a01);
    *reinterpret_cast<float2*>(&out[(size_t)(r0 + 1) * ldo + c0]) = make_float2(a10, a11);
    *reinterpret_cast<float2*>(&out[(size_t)(r0 + 2) * ldo + c0]) = make_float2(a20, a21);
    *reinterpret_cast<float2*>(&out[(size_t)(r0 + 3) * ldo + c0]) = make_float2(a30, a31);
}

// ---------------------------------------------------------------------------
// Precompute P[16384,1024] = x[16384,512] @ Wxh[512,1024]   (parallel node)
// tile 128x128, BK=16, 256 threads, 8x8 microtile
// ---------------------------------------------------------------------------
__global__ __launch_bounds__(256) void gemm_P(
    const float* __restrict__ x, const float* __restrict__ Wxh)
{
    __shared__ __align__(16) float Xs[16][132];
    __shared__ __align__(16) float Ws[16][132];
    const int tid  = threadIdx.x;
    const int row0 = blockIdx.x * 128;
    const int col0 = blockIdx.y * 128;
    const int c0 = (tid & 15) * 8;
    const int r0 = (tid >> 4) * 8;

    float acc[8][8];
    #pragma unroll
    for (int r = 0; r < 8; r++)
        #pragma unroll
        for (int c = 0; c < 8; c++) acc[r][c] = 0.f;

    for (int kt = 0; kt < IN_; kt += 16) {
        #pragma unroll
        for (int i = tid; i < 128 * 16; i += 256) {
            int r = i >> 4, kk = i & 15;
            Xs[kk][r] = x[(size_t)(row0 + r) * IN_ + kt + kk];
        }
        #pragma unroll
        for (int i = tid; i < 128 * 16; i += 256) {
            int kk = i >> 7, c = i & 127;
            Ws[kk][c] = Wxh[(size_t)(kt + kk) * HID_ + col0 + c];
        }
        __syncthreads();
        #pragma unroll
        for (int kk = 0; kk < 16; kk++) {
            float4 x0 = *reinterpret_cast<const float4*>(&Xs[kk][r0]);
            float4 x1 = *reinterpret_cast<const float4*>(&Xs[kk][r0 + 4]);
            float4 w0 = *reinterpret_cast<const float4*>(&Ws[kk][c0]);
            float4 w1 = *reinterpret_cast<const float4*>(&Ws[kk][c0 + 4]);
            float av[8] = {x0.x, x0.y, x0.z, x0.w, x1.x, x1.y, x1.z, x1.w};
            float wv[8] = {w0.x, w0.y, w0.z, w0.w, w1.x, w1.y, w1.z, w1.w};
            #pragma unroll
            for (int r = 0; r < 8; r++)
                #pragma unroll
                for (int c = 0; c < 8; c++) acc[r][c] += av[r] * wv[c];
        }
        __syncthreads();
    }
    #pragma unroll
    for (int r = 0; r < 8; r++) {
        float4* o0 = reinterpret_cast<float4*>(&g_P[(size_t)(row0 + r0 + r) * HID_ + col0 + c0]);
        *o0       = make_float4(acc[r][0], acc[r][1], acc[r][2], acc[r][3]);
        *(o0 + 1) = make_float4(acc[r][4], acc[r][5], acc[r][6], acc[r][7]);
    }
}

// ---------------------------------------------------------------------------
// Init: G = 0, U = 0, m = m_prev, barrier state = 0
// ---------------------------------------------------------------------------
__global__ void k_init(const float* __restrict__ m_prev) {
    int idx = blockIdx.x * 256 + threadIdx.x;   // < 81920 float4 slots
    if (blockIdx.x == 0) {
        for (int j = threadIdx.x; j < NBMAX * 32; j += 256) g_arrive[j] = 0;
        if (threadIdx.x == 0) g_go = 0;
    }
    float4 z = make_float4(0.f, 0.f, 0.f, 0.f);
    if (idx < 16384) {
        *reinterpret_cast<float4*>(&g_G[idx * 4]) = z;
    } else if (idx < 49152) {
        *reinterpret_cast<float4*>(&g_U[(idx - 16384) * 4]) = z;
    } else if (idx < 81920) {
        int e = (idx - 49152) * 4;
        *reinterpret_cast<float4*>(&g_m[e]) = *reinterpret_cast<const float4*>(&m_prev[e]);
    }
}

// ---------------------------------------------------------------------------
// Persistent scan: phase 0 seeds partials from m_prev, then T steps of
//   A: fold Gparts into G; h = tanh(P_t + G + bh)
//   B: Hpart[s] = h[:, s*64:(s+1)*64] @ Whm^T over active cols (16 K-slices)
//   C: fold Uparts into U (bj<k); m_new = U + bm + sum Hpart; dm; write out
//   D: Gpart/Upart = dm @ W^T  (overwrite pending partials)
// with a grid barrier between phases. Fold/overwrite invariant: a partial is
// folded at exactly the steps where it is rewritten, and fold precedes rewrite.
// ---------------------------------------------------------------------------
__global__ __launch_bounds__(NT, 1) void k_scan(
    const float* __restrict__ m_prev,
    const float* __restrict__ Whm, const float* __restrict__ Wmm,
    const float* __restrict__ Wmh,
    const float* __restrict__ bm,  const float* __restrict__ bh,
    float* __restrict__ out, int full, int tail)
{
    __shared__ __align__(16) float sm[2048 + 1024];
    const int bid = blockIdx.x;
    const int gsz = gridDim.x;
    const int tid = threadIdx.x;
    unsigned ep = 0;

    // ---- phase 0: seed partials from m_prev ----
    for (int tt = bid; tt < 768; tt += gsz) {
        if (tt < 256) {            // Gpart: 8 K-slices (K=256) x 32 col tiles
            int s = tt & 7, ct = tt >> 3;
            tile64x32(m_prev + s * 256, M_,
                      Wmh + (size_t)(ct * 32) * M_ + s * 256, M_, 256,
                      g_Gpart + (size_t)s * B_ * HID_ + ct * 32, HID_, sm);
        } else {                   // Upart: 8 blocks x 8 slices x 8 col tiles
            int u = tt - 256;
            int s = u & 7, ct = (u >> 3) & 7, bj = u >> 6;
            int slice = (NMOD_ - bj) * 32;
            int i0 = bj * MEM_ + s * slice;
            tile64x32(m_prev + i0, M_,
                      Wmm + (size_t)(bj * MEM_ + ct * 32) * M_ + i0, M_, slice,
                      g_Upart + (size_t)(bj * 8 + s) * B_ * MEM_ + ct * 32, MEM_, sm);
        }
    }
    gsync(++ep);

    for (int t = 0; t < T_; t++) {
        int k = 0;
        while (k < NMOD_ && (t & ((1 << k) - 1)) == 0) k++;

        // ---- phase A: fold G, compute h ----
        for (int i = bid * NT + tid; i < 16384; i += gsz * NT) {
            int e = i * 4;
            float4 g = *reinterpret_cast<float4*>(&g_G[e]);
            #pragma unroll
            for (int s = 0; s < 8; s++) {
                float4 p = *reinterpret_cast<const float4*>(&g_Gpart[(size_t)s * B_ * HID_ + e]);
                g.x += p.x; g.y += p.y; g.z += p.z; g.w += p.w;
            }
            *reinterpret_cast<float4*>(&g_G[e]) = g;
            float4 pp = *reinterpret_cast<const float4*>(&g_P[(size_t)t * B_ * HID_ + e]);
            float4 bb = *reinterpret_cast<const float4*>(&bh[e & (HID_ - 1)]);
            float4 h;
            h.x = tanhf(pp.x + g.x + bb.x);
            h.y = tanhf(pp.y + g.y + bb.y);
            h.z = tanhf(pp.z + g.z + bb.z);
            h.w = tanhf(pp.w + g.w + bb.w);
            *reinterpret_cast<float4*>(&g_h[e]) = h;
        }
        gsync(++ep);

        // ---- phase B: Hpart slices over active columns ----
        {
            int nB = 128 * k;   // 16 slices x 8k col tiles of 32
            for (int tt = bid; tt < nB; tt += gsz) {
                int s = tt & 15, ct = tt >> 4;
                int j0 = ct * 32;
                tile64x32(g_h + s * 64, HID_,
                          Whm + (size_t)j0 * HID_ + s * 64, HID_, 64,
                          g_Hpart + (size_t)s * B_ * M_ + j0, M_, sm);
            }
        }
        gsync(++ep);

        // ---- phase C: finalize m_t, dm, write out ----
        {
            float* outp = full ? out + (size_t)t * B_ * M_
                               : (t == T_ - 1 ? out : (float*)0);
            for (int i = bid * NT + tid; i < 32768; i += gsz * NT) {
                int e = i * 4;
                int b = e >> 11, j = e & (M_ - 1);
                float4 res;
                if (j < k * MEM_) {
                    int bj = j >> 8, jc = j & (MEM_ - 1);
                    float4 u = *reinterpret_cast<float4*>(&g_U[e]);
                    size_t pb = (size_t)(bj * 8) * B_ * MEM_ + (size_t)b * MEM_ + jc;
                    #pragma unroll
                    for (int s = 0; s < 8; s++) {
                        float4 p = *reinterpret_cast<const float4*>(&g_Upart[pb + (size_t)s * B_ * MEM_]);
                        u.x += p.x; u.y += p.y; u.z += p.z; u.w += p.w;
                    }
                    *reinterpret_cast<float4*>(&g_U[e]) = u;   // fold
                    float4 bb = *reinterpret_cast<const float4*>(&bm[j]);
                    float4 mn = make_float4(u.x + bb.x, u.y + bb.y, u.z + bb.z, u.w + bb.w);
                    #pragma unroll
                    for (int s = 0; s < 16; s++) {
                        float4 hp = *reinterpret_cast<const float4*>(&g_Hpart[(size_t)s * B_ * M_ + e]);
                        mn.x += hp.x; mn.y += hp.y; mn.z += hp.z; mn.w += hp.w;
                    }
                    float4 old = *reinterpret_cast<const float4*>(&g_m[e]);
                    *reinterpret_cast<float4*>(&g_dm[e]) =
                        make_float4(mn.x - old.x, mn.y - old.y, mn.z - old.z, mn.w - old.w);
                    *reinterpret_cast<float4*>(&g_m[e]) = mn;
                    res = mn;
                } else {
                    res = *reinterpret_cast<const float4*>(&g_m[e]);
                }
                if (outp) *reinterpret_cast<float4*>(&outp[e]) = res;
                if (tail && t == T_ - 1)
                    *reinterpret_cast<float4*>(&out[(size_t)T_ * B_ * M_ + e]) = res;
            }
        }
        gsync(++ep);

        // ---- phase D: overwrite pending partials from dm ----
        if (t < T_ - 1) {
            int nD = 256 + 64 * k;
            for (int tt = bid; tt < nD; tt += gsz) {
                if (tt < 256) {        // Gpart: 8 slices (K=k*32) x 32 col tiles
                    int s = tt & 7, ct = tt >> 3;
                    int kw = k * 32;
                    tile64x32(g_dm + s * kw, M_,
                              Wmh + (size_t)(ct * 32) * M_ + s * kw, M_, kw,
                              g_Gpart + (size_t)s * B_ * HID_ + ct * 32, HID_, sm);
                } else {               // Upart: bj<k blocks x 8 slices x 8 col tiles
                    int u = tt - 256;
                    int s = u & 7, ct = (u >> 3) & 7, bj = u >> 6;
                    int slice = (k - bj) * 32;
                    int i0 = bj * MEM_ + s * slice;
                    tile64x32(g_dm + i0, M_,
                              Wmm + (size_t)(bj * MEM_ + ct * 32) * M_ + i0, M_, slice,
                              g_Upart + (size_t)(bj * 8 + s) * B_ * MEM_ + ct * 32, MEM_, sm);
                }
            }
            gsync(++ep);
        }
    }
}

// ---------------------------------------------------------------------------
extern "C" void kernel_launch(void* const* d_in, const int* in_sizes, int n_in,
                              void* d_out, int out_size) {
    const float* x      = (const float*)d_in[0];
    const float* m_prev = (const float*)d_in[1];
    const float* Wxh    = (const float*)d_in[2];
    const float* Whm    = (const float*)d_in[3];
    const float* Wmm    = (const float*)d_in[4];
    const float* Wmh    = (const float*)d_in[5];
    const float* bm     = (const float*)d_in[6];
    const float* bh     = (const float*)d_in[7];
    float* out = (float*)d_out;

    const size_t outs_elems = (size_t)T_ * B_ * M_;
    const int full = ((size_t)out_size >= outs_elems) ? 1 : 0;
    const int tail = ((size_t)out_size >= outs_elems + (size_t)B_ * M_) ? 1 : 0;

    int dev = 0, sms = NBMAX;
    cudaGetDevice(&dev);
    if (cudaDeviceGetAttribute(&sms, cudaDevAttrMultiProcessorCount, dev) != cudaSuccess)
        sms = NBMAX;
    int grid = sms < NBMAX ? sms : NBMAX;

    gemm_P<<<dim3(128, 8), 256>>>(x, Wxh);
    k_init<<<320, 256>>>(m_prev);
    k_scan<<<grid, NT>>>(m_prev, Whm, Wmm, Wmh, bm, bh, out, full, tail);
}